// round 7
// baseline (speedup 1.0000x reference)
#include <cuda_runtime.h>
#include <cuda_bf16.h>

#define BB 64
#define NQ 300
#define NP 320            // padded column stride (k=0..4, 64 cols each)
#define TT 30
#define BIGF  1e18f
#define HUGEF 1e30f

// per-batch partial sums: [B][3] = {bce_sum, l1_sum, giou_sum}
__device__ float g_partials[BB * 3];
__device__ unsigned g_count;   // zero-init; last block resets each launch

// order-isomorphic float <-> u32 key (exact round-trip)
__device__ __forceinline__ unsigned fkey(float f) {
    unsigned b = __float_as_uint(f);
    return b ^ (((unsigned)((int)b >> 31)) | 0x80000000u);
}
__device__ __forceinline__ float funkey(unsigned k) {
    unsigned m = ((unsigned)((int)(~k) >> 31)) | 0x80000000u;
    return __uint_as_float(k ^ m);
}
__device__ __forceinline__ unsigned long long pack2(float x, float y) {
    unsigned long long r; asm("mov.b64 %0,{%1,%2};" : "=l"(r) : "f"(x), "f"(y)); return r;
}
__device__ __forceinline__ void unpack2(unsigned long long v, float& x, float& y) {
    asm("mov.b64 {%0,%1},%2;" : "=f"(x), "=f"(y) : "l"(v));
}
// two independent round-to-nearest f32 adds in one instruction (bit-exact per lane)
__device__ __forceinline__ unsigned long long add2(unsigned long long a, unsigned long long b) {
    unsigned long long r; asm("add.rn.f32x2 %0,%1,%2;" : "=l"(r) : "l"(a), "l"(b)); return r;
}
// pack (key:high32, j:low32) -> u64; u64 min gives (min key, then min j) = first-index ties
__device__ __forceinline__ unsigned long long packkj(unsigned key, unsigned j) {
    unsigned long long r; asm("mov.b64 %0,{%1,%2};" : "=l"(r) : "r"(j), "r"(key)); return r;
}
__device__ __forceinline__ unsigned long long umin64(unsigned long long a, unsigned long long b) {
    return a < b ? a : b;
}

__global__ __launch_bounds__(256)
void detr_criterion_kernel(const float* __restrict__ pred_boxes,
                           const float* __restrict__ pred_classes,
                           const float* __restrict__ targets,
                           float* __restrict__ out)
{
    __shared__ float cost[TT * NP];     // [t][n], padded cols zeroed
    __shared__ float4 pb4[NQ];          // staged pred boxes
    __shared__ float4 tg4[TT];          // staged targets
    __shared__ float vneg[NP];          // -v[j]; pads = +1e30 (mask)
    __shared__ float spcfro[NP];        // frozen spc at selection (= minVal then)
    __shared__ int   path_sh[NP];
    __shared__ int2  combo[NQ];         // {row4col[j], bits(u[row4col[j]])}
    __shared__ int   row4col[NQ];
    __shared__ unsigned char matched[NQ];
    __shared__ float u[TT];
    __shared__ int   col4row[TT];
    __shared__ int   sorted_idx[TT];
    __shared__ float warpsum[8];
    __shared__ float l1s[TT];
    __shared__ float gis[TT];
    __shared__ int   s_last;

    const int b   = blockIdx.x;
    const int tid = threadIdx.x;
    const float* pbg = pred_boxes   + (size_t)b * NQ * 4;
    const float* pc  = pred_classes + (size_t)b * NQ;
    const float* tgg = targets      + (size_t)b * TT * 4;

    // ---- stage boxes in shared (coalesced)
    for (int n = tid; n < NQ; n += blockDim.x) pb4[n] = ((const float4*)pbg)[n];
    if (tid < TT) tg4[tid] = ((const float4*)tgg)[tid];
    __syncthreads();

    // ---- cost matrix (padded): cost[t][n] = -pc[n] - giou + L1
    for (int idx = tid; idx < TT * NP; idx += blockDim.x) {
        int t = idx / NP, n = idx - t * NP;
        float cv = 0.0f;
        if (n < NQ) {
            float4 p = pb4[n];
            float4 g = tg4[t];
            float ax0 = p.x, ay0 = p.y, ax1 = p.x + p.z, ay1 = p.y + p.w;
            float bx0 = g.x, by0 = g.y, bx1 = g.x + g.z, by1 = g.y + g.w;
            float area_a = (ax1 - ax0) * (ay1 - ay0);
            float area_b = (bx1 - bx0) * (by1 - by0);
            float iw = fmaxf(fminf(ax1, bx1) - fmaxf(ax0, bx0), 0.0f);
            float ih = fmaxf(fminf(ay1, by1) - fmaxf(ay0, by0), 0.0f);
            float inter = iw * ih;
            float uni = area_a + area_b - inter;
            float iou = inter / uni;
            float cw = fmaxf(fmaxf(ax1, bx1) - fminf(ax0, bx0), 0.0f);
            float ch = fmaxf(fmaxf(ay1, by1) - fminf(ay0, by0), 0.0f);
            float areac = cw * ch;
            float giou = iou - (areac - uni) / areac;
            float l1 = fabsf(p.x - g.x) + fabsf(p.y - g.y) + fabsf(p.z - g.z) + fabsf(p.w - g.w);
            cv = -pc[n] - giou + l1;
        }
        cost[idx] = cv;
    }
    for (int j = tid; j < NP; j += blockDim.x) vneg[j] = (j < NQ) ? 0.0f : HUGEF;
    for (int j = tid; j < NQ; j += blockDim.x) { row4col[j] = -1; matched[j] = 0; }
    if (tid < TT) { u[tid] = 0.0f; col4row[tid] = -1; }
    __syncthreads();

    // ---- Hungarian (shortest augmenting path), warp 0, warp-synchronous
    if (tid < 32) {
        const int lane = tid;
        const unsigned FULL = 0xffffffffu;
        const int lane2 = 2 * lane;
        const unsigned KBIG = fkey(BIGF);

        for (int row = 0; row < TT; ++row) {
            // per-search state refresh
            float    av[10];      // vneg per column; +1e30 once SC'd (mask)
            unsigned spk[10];     // spc as order-isomorphic keys
            #pragma unroll
            for (int k = 0; k < 5; ++k) {
                float2 vn = *(const float2*)&vneg[64 * k + lane2];
                av[2 * k] = vn.x; av[2 * k + 1] = vn.y;
                spk[2 * k] = KBIG; spk[2 * k + 1] = KBIG;
            }
            for (int p = lane; p < NQ; p += 32) {
                int r = row4col[p];
                combo[p] = make_int2(r, (r >= 0) ? __float_as_int(u[r]) : 0);
            }
            unsigned SRmask = 0;
            int   cur_i  = row;
            float u_cur  = u[row];
            float minVal = 0.0f;
            int   sink   = -1;
            __syncwarp();

            while (sink < 0) {
                SRmask |= 1u << cur_i;
                const float2* crow2 = (const float2*)&cost[cur_i * NP];
                unsigned long long mv2 = pack2(minVal, minVal);
                unsigned long long nu2 = pack2(-u_cur, -u_cur);

                unsigned long long cnd[10];
                #pragma unroll
                for (int k = 0; k < 5; ++k) {
                    float2 c2 = crow2[k * 32 + lane];
                    // EXACT ref rounding: ((minVal + c) - u) - v
                    unsigned long long r2 = add2(add2(add2(pack2(c2.x, c2.y), mv2), nu2),
                                                 pack2(av[2 * k], av[2 * k + 1]));
                    float rx, ry; unpack2(r2, rx, ry);
                    int j0 = 64 * k + lane2;
                    unsigned kx = fkey(rx), ky = fkey(ry);
                    if (kx < spk[2 * k])     { spk[2 * k] = kx;     path_sh[j0] = cur_i; }
                    if (ky < spk[2 * k + 1]) { spk[2 * k + 1] = ky; path_sh[j0 + 1] = cur_i; }
                    cnd[2 * k]     = packkj(spk[2 * k],     (unsigned)j0);
                    cnd[2 * k + 1] = packkj(spk[2 * k + 1], (unsigned)(j0 + 1));
                }
                // lane-local argmin: u64 tree (key major, index minor -> first-index ties)
                unsigned long long m01 = umin64(cnd[0], cnd[1]);
                unsigned long long m23 = umin64(cnd[2], cnd[3]);
                unsigned long long m45 = umin64(cnd[4], cnd[5]);
                unsigned long long m67 = umin64(cnd[6], cnd[7]);
                unsigned long long m89 = umin64(cnd[8], cnd[9]);
                unsigned long long m03 = umin64(m01, m23);
                unsigned long long m47 = umin64(m45, m67);
                unsigned long long best = umin64(umin64(m03, m47), m89);
                unsigned bestKey = (unsigned)(best >> 32);
                unsigned bestJ   = (unsigned)best;
                // cross-lane argmin, first-index tie-break
                unsigned kmin = __reduce_min_sync(FULL, bestKey);
                unsigned jc   = (bestKey == kmin) ? bestJ : 0xffffffffu;
                unsigned jmin = __reduce_min_sync(FULL, jc);
                minVal = funkey(kmin);                 // exact round-trip

                if (lane == 0) spcfro[jmin] = minVal;  // frozen spc of SC'd column
                // freeze column jmin (mask from argmin + huge future reds)
                bool own = (lane == (int)((jmin & 63u) >> 1));
                int  slot = (int)(((jmin >> 6) << 1) | (jmin & 1u));
                #pragma unroll
                for (int s = 0; s < 10; ++s)
                    if (own && slot == s) { spk[s] = KBIG; av[s] = HUGEF; }

                int2 cb = combo[jmin];                 // {row4col, u bits}
                if (cb.x < 0) sink = (int)jmin;
                else { cur_i = cb.x; u_cur = __int_as_float(cb.y); }
            }
            __syncwarp();   // spcfro/path stores visible warp-wide

            // ---- dual v update: vneg[j] += (minVal - spc[j]) for SC columns
            #pragma unroll
            for (int k = 0; k < 5; ++k) {
                #pragma unroll
                for (int h = 0; h < 2; ++h) {
                    int j = 64 * k + lane2 + h;
                    int s = 2 * k + h;
                    if (j < NQ && av[s] == HUGEF)
                        vneg[j] = vneg[j] + (minVal - spcfro[j]);
                }
            }
            // ---- dual u update (reads pre-augmentation col4row)
            if (lane < TT) {
                if (lane == row) u[lane] += minVal;
                else if ((SRmask >> lane) & 1u) u[lane] += minVal - spcfro[col4row[lane]];
            }
            __syncwarp();

            // ---- augment along alternating path (serial, lane 0)
            if (lane == 0) {
                int j = sink;
                for (;;) {
                    int i = path_sh[j];
                    row4col[j] = i;
                    int nj = col4row[i];
                    col4row[i] = j;
                    if (i == row) break;
                    j = nj;
                }
            }
            __syncwarp();
        }

        // boxes_idx = sort(col4row); mark matched set
        if (lane == 0) {
            for (int i = 0; i < TT; ++i) sorted_idx[i] = col4row[i];
            for (int i = 1; i < TT; ++i) {
                int key = sorted_idx[i];
                int k = i - 1;
                while (k >= 0 && sorted_idx[k] > key) { sorted_idx[k + 1] = sorted_idx[k]; --k; }
                sorted_idx[k + 1] = key;
            }
            for (int i = 0; i < TT; ++i) matched[sorted_idx[i]] = 1;
        }
    }
    __syncthreads();

    // ---- BCE over all N queries
    float local = 0.0f;
    for (int n = tid; n < NQ; n += blockDim.x) {
        float p = pc[n];
        float lg = matched[n] ? logf(p) : logf(1.0f - p);
        local += -fmaxf(lg, -100.0f);
    }
    #pragma unroll
    for (int off = 16; off; off >>= 1)
        local += __shfl_down_sync(0xffffffffu, local, off);
    if ((tid & 31) == 0) warpsum[tid >> 5] = local;

    // ---- L1 + GIoU on matched (sorted-index) pairs
    if (tid < TT) {
        int t = tid;
        int n = sorted_idx[t];
        float4 p = pb4[n];
        float4 g = tg4[t];
        l1s[t] = fabsf(p.x - g.x) + fabsf(p.y - g.y) + fabsf(p.z - g.z) + fabsf(p.w - g.w);

        float ax0 = p.x, ay0 = p.y, ax1 = p.x + p.z, ay1 = p.y + p.w;
        float bx0 = g.x, by0 = g.y, bx1 = g.x + g.z, by1 = g.y + g.w;
        float area_a = (ax1 - ax0) * (ay1 - ay0);
        float area_b = (bx1 - bx0) * (by1 - by0);
        float iw = fmaxf(fminf(ax1, bx1) - fmaxf(ax0, bx0), 0.0f);
        float ih = fmaxf(fminf(ay1, by1) - fmaxf(ay0, by0), 0.0f);
        float inter = iw * ih;
        float uni = area_a + area_b - inter;
        float iou = inter / uni;
        float cw = fmaxf(fmaxf(ax1, bx1) - fminf(ax0, bx0), 0.0f);
        float ch = fmaxf(fmaxf(ay1, by1) - fminf(ay0, by0), 0.0f);
        float areac = cw * ch;
        float giou = iou - (areac - uni) / areac;
        gis[t] = 1.0f - giou;
    }
    __syncthreads();

    // ---- per-batch partials + last-block final reduction (deterministic order)
    if (tid == 0) {
        float bce = 0.0f;
        #pragma unroll
        for (int w = 0; w < 8; ++w) bce += warpsum[w];
        float l1 = 0.0f, gi = 0.0f;
        for (int t = 0; t < TT; ++t) { l1 += l1s[t]; gi += gis[t]; }
        g_partials[b * 3 + 0] = bce;
        g_partials[b * 3 + 1] = l1;
        g_partials[b * 3 + 2] = gi;
        __threadfence();
        unsigned ticket = atomicAdd(&g_count, 1u);
        s_last = (ticket == BB - 1) ? 1 : 0;
    }
    __syncthreads();

    if (s_last) {
        __threadfence();
        if (tid < 3) {
            float s = 0.0f;
            for (int bb2 = 0; bb2 < BB; ++bb2) s += g_partials[bb2 * 3 + tid];
            float denom = (tid == 0) ? (float)(BB * NQ) : (float)(BB * TT);
            out[tid] = s / denom;
        }
        if (tid == 0) g_count = 0;   // reset for next graph replay
    }
}

extern "C" void kernel_launch(void* const* d_in, const int* in_sizes, int n_in,
                              void* d_out, int out_size)
{
    const float* pred_boxes = nullptr;
    const float* pred_classes = nullptr;
    const float* targets = nullptr;
    for (int i = 0; i < n_in; ++i) {
        if (in_sizes[i] == BB * NQ * 4)      pred_boxes   = (const float*)d_in[i];
        else if (in_sizes[i] == BB * NQ)     pred_classes = (const float*)d_in[i];
        else if (in_sizes[i] == BB * TT * 4) targets      = (const float*)d_in[i];
    }
    detr_criterion_kernel<<<BB, 256>>>(pred_boxes, pred_classes, targets, (float*)d_out);
}